// round 15
// baseline (speedup 1.0000x reference)
#include <cuda_runtime.h>
#include <cstdint>

// ExpandMask: x [B=64, 1, L=262144] f32 -> out [B, 1, 2L] float (0.0/1.0)
//   out[2i]   = (x[i-1] + x[i] + x[i+1] > 0.5)   (zero taps outside row)
//   out[2i+1] = (x[i]   + x[i+1]        > 0.5)
//
// FINAL (= R11/R13, lowest measured kernel time 28.16us).
// BLOCK=256, CHUNKS=4, one output float4 per lane per chunk:
//   - dense LDG.64 loads, default caching
//   - dense STG.128 stores, default write-back (beat .cs and .wt)
//   - halo taps via warp shuffle; lane 0/31 edge taps via scalar loads
//
// Converged at the DRAM write roofline: ~144MB traffic per launch
// (128MB mandatory float32 output writes + ~15MB steady-state reads) at
// ~5.0-5.1TB/s mixed-stream bandwidth. A/B'd and rejected as neutral or
// worse: .cs/.wt stores, .cs loads, v8+evict_last loads, 256-bit stores,
// MLP 2/8, BLOCK=1024, per-thread-blocked layouts (wavefront amplification),
// index-math hoisting. R14 (v8 accesses, full-sector stores) reproduced the
// identical 5.03TB/s, proving the ceiling is path-bound, not access-shaped.

static constexpr int L = 262144;                    // input row length
static constexpr int OUT_F4_PER_ROW = (2 * L) / 4;  // 131072 = 2^17
static constexpr int CHUNKS = 4;
static constexpr int BLOCK = 256;

__global__ void __launch_bounds__(BLOCK) expand_mask_kernel(
    const float* __restrict__ x, float4* __restrict__ out)
{
    const int lane = threadIdx.x & 31;
    const int block_base = blockIdx.x * (BLOCK * CHUNKS);

    // Front-batch 4 independent dense float2 loads (MLP = 4).
    int o[CHUNKS], ibase[CHUNKS], p[CHUNKS];
    float2 e[CHUNKS];
    #pragma unroll
    for (int c = 0; c < CHUNKS; c++) {
        o[c] = block_base + c * BLOCK + threadIdx.x;     // output float4 idx
        const int r = o[c] >> 17;                        // row (OUT_F4_PER_ROW = 2^17)
        p[c] = o[c] & (OUT_F4_PER_ROW - 1);              // position within row
        ibase[c] = r * L + 2 * p[c];                     // input float index
        e[c] = *reinterpret_cast<const float2*>(x + ibase[c]);
    }

    #pragma unroll
    for (int c = 0; c < CHUNKS; c++) {
        // Halo taps: left = x[2p-1], right = x[2p+2] (zero outside row).
        float left  = __shfl_up_sync(0xffffffffu, e[c].y, 1);
        float right = __shfl_down_sync(0xffffffffu, e[c].x, 1);
        if (lane == 0)
            left  = (p[c] == 0) ? 0.0f : __ldg(x + ibase[c] - 1);
        if (lane == 31)
            right = (p[c] == OUT_F4_PER_ROW - 1) ? 0.0f : __ldg(x + ibase[c] + 2);

        const float s01 = e[c].x + e[c].y;   // x[2p] + x[2p+1]
        float4 ov;
        ov.x = (left + s01)     > 0.5f ? 1.0f : 0.0f;  // out[4p]
        ov.y =  s01             > 0.5f ? 1.0f : 0.0f;  // out[4p+1]
        ov.z = (s01 + right)    > 0.5f ? 1.0f : 0.0f;  // out[4p+2]
        ov.w = (e[c].y + right) > 0.5f ? 1.0f : 0.0f;  // out[4p+3]

        out[o[c]] = ov;   // default write-back STG.128
    }
}

extern "C" void kernel_launch(void* const* d_in, const int* in_sizes, int n_in,
                              void* d_out, int out_size)
{
    const float* x = (const float*)d_in[0];
    float4* out = (float4*)d_out;

    const int total_out_f4 = (2 * in_sizes[0]) / 4;      // 8388608
    const int grid = total_out_f4 / (BLOCK * CHUNKS);    // 8192

    expand_mask_kernel<<<grid, BLOCK>>>(x, out);
}

// round 16
// speedup vs baseline: 1.0082x; 1.0082x over previous
#include <cuda_runtime.h>
#include <cstdint>

// ExpandMask: x [B=64, 1, L=262144] f32 -> out [B, 1, 2L] float (0.0/1.0)
//   out[2i]   = (x[i-1] + x[i] + x[i+1] > 0.5)   (zero taps outside row)
//   out[2i+1] = (x[i]   + x[i+1]        > 0.5)
//
// R16: final A/B cell — the winning coalesced layout (one output float4 per
// lane per chunk, dense LDG.64 + dense STG.128 write-back, shuffle halos)
// with CHUNKS=2 (grid 16384): finer wave quantization / smaller tail, lower
// register count. All other axes closed by R5-R15 A/Bs; kernel is at the
// DRAM write roofline (~144MB/launch @ ~5.0-5.1TB/s, 128MB mandatory writes).

static constexpr int L = 262144;                    // input row length
static constexpr int OUT_F4_PER_ROW = (2 * L) / 4;  // 131072 = 2^17
static constexpr int CHUNKS = 2;
static constexpr int BLOCK = 256;

__global__ void __launch_bounds__(BLOCK) expand_mask_kernel(
    const float* __restrict__ x, float4* __restrict__ out)
{
    const int lane = threadIdx.x & 31;
    const int block_base = blockIdx.x * (BLOCK * CHUNKS);

    // Front-batch independent dense float2 loads.
    int o[CHUNKS], ibase[CHUNKS], p[CHUNKS];
    float2 e[CHUNKS];
    #pragma unroll
    for (int c = 0; c < CHUNKS; c++) {
        o[c] = block_base + c * BLOCK + threadIdx.x;     // output float4 idx
        const int r = o[c] >> 17;                        // row (OUT_F4_PER_ROW = 2^17)
        p[c] = o[c] & (OUT_F4_PER_ROW - 1);              // position within row
        ibase[c] = r * L + 2 * p[c];                     // input float index
        e[c] = *reinterpret_cast<const float2*>(x + ibase[c]);
    }

    #pragma unroll
    for (int c = 0; c < CHUNKS; c++) {
        // Halo taps: left = x[2p-1], right = x[2p+2] (zero outside row).
        float left  = __shfl_up_sync(0xffffffffu, e[c].y, 1);
        float right = __shfl_down_sync(0xffffffffu, e[c].x, 1);
        if (lane == 0)
            left  = (p[c] == 0) ? 0.0f : __ldg(x + ibase[c] - 1);
        if (lane == 31)
            right = (p[c] == OUT_F4_PER_ROW - 1) ? 0.0f : __ldg(x + ibase[c] + 2);

        const float s01 = e[c].x + e[c].y;   // x[2p] + x[2p+1]
        float4 ov;
        ov.x = (left + s01)     > 0.5f ? 1.0f : 0.0f;  // out[4p]
        ov.y =  s01             > 0.5f ? 1.0f : 0.0f;  // out[4p+1]
        ov.z = (s01 + right)    > 0.5f ? 1.0f : 0.0f;  // out[4p+2]
        ov.w = (e[c].y + right) > 0.5f ? 1.0f : 0.0f;  // out[4p+3]

        out[o[c]] = ov;   // default write-back STG.128
    }
}

extern "C" void kernel_launch(void* const* d_in, const int* in_sizes, int n_in,
                              void* d_out, int out_size)
{
    const float* x = (const float*)d_in[0];
    float4* out = (float4*)d_out;

    const int total_out_f4 = (2 * in_sizes[0]) / 4;      // 8388608
    const int grid = total_out_f4 / (BLOCK * CHUNKS);    // 16384

    expand_mask_kernel<<<grid, BLOCK>>>(x, out);
}